// round 16
// baseline (speedup 1.0000x reference)
#include <cuda_runtime.h>
#include <cuda_fp16.h>
#include <cstdint>

// ---------------------------------------------------------------------------
// InformerStandard: B=8, P=16, L=1024, D=1024, H=16(dk=64), HZN=96, FF=32, 2 layers
// Round 16 (retry of 15; infra failed): gemm_qkv at 512 threads (16 warps,
// 4x4 warp grid, 32x32 warp tile) -> 32 warps/SM. Bit-identical math.
// ---------------------------------------------------------------------------

#define B_  8
#define L_  1024
#define D_  1024
#define H_  16
#define DK_ 64
#define FF_ 32
#define U_  6
#define HZN_ 96
#define CAND 32
#define NROWS (B_*L_)   // 8192

__device__ float  g_h[B_*L_*D_];
__device__ __half g_hh[B_*L_*D_];
__device__ __half g_hl[B_*L_*D_];
__device__ __half g_whh[6*D_*D_];
__device__ __half g_whl[6*D_*D_];
__device__ float  g_Q[B_*L_*D_];
__device__ float  g_K[B_*L_*D_];
__device__ float  g_V[B_*L_*D_];
__device__ float  g_rowmax[B_*H_*L_];
__device__ int    g_top[B_*H_*U_];
__device__ float  g_ctx[B_*H_*U_*DK_];
__device__ float  g_meanp[8*B_*D_];
__device__ float  g_mean[B_*D_];

#define DI __device__ __forceinline__

DI uint32_t smem_u32(const void* p) {
    uint32_t a;
    asm("{ .reg .u64 t; cvta.to.shared.u64 t, %1; cvt.u32.u64 %0, t; }" : "=r"(a) : "l"(p));
    return a;
}
DI uint32_t lds_u32(uint32_t a) {
    uint32_t v; asm volatile("ld.shared.b32 %0, [%1];" : "=r"(v) : "r"(a)); return v;
}
DI void ldsm_x4(uint32_t& r0, uint32_t& r1, uint32_t& r2, uint32_t& r3, uint32_t addr) {
    asm volatile("ldmatrix.sync.aligned.m8n8.x4.shared.b16 {%0,%1,%2,%3}, [%4];"
                 : "=r"(r0), "=r"(r1), "=r"(r2), "=r"(r3) : "r"(addr));
}
DI void cp_async16(uint32_t dst, const void* src) {
    asm volatile("cp.async.cg.shared.global [%0], [%1], 16;" :: "r"(dst), "l"(src));
}
DI void cp_commit() { asm volatile("cp.async.commit_group;"); }
template<int N> DI void cp_wait() { asm volatile("cp.async.wait_group %0;" :: "n"(N)); }

DI void mma_f16(float* d, const uint32_t* a, uint32_t b0, uint32_t b1) {
    asm volatile("mma.sync.aligned.m16n8k16.row.col.f32.f16.f16.f32 "
                 "{%0,%1,%2,%3}, {%4,%5,%6,%7}, {%8,%9}, {%0,%1,%2,%3};"
                 : "+f"(d[0]), "+f"(d[1]), "+f"(d[2]), "+f"(d[3])
                 : "r"(a[0]), "r"(a[1]), "r"(a[2]), "r"(a[3]), "r"(b0), "r"(b1));
}
DI void mma_tf32(float* d, const uint32_t* a, uint32_t b0, uint32_t b1) {
    asm volatile("mma.sync.aligned.m16n8k8.row.col.f32.tf32.tf32.f32 "
                 "{%0,%1,%2,%3}, {%4,%5,%6,%7}, {%8,%9}, {%0,%1,%2,%3};"
                 : "+f"(d[0]), "+f"(d[1]), "+f"(d[2]), "+f"(d[3])
                 : "r"(a[0]), "r"(a[1]), "r"(a[2]), "r"(a[3]), "r"(b0), "r"(b1));
}

DI void split_f16(float v, __half& hi, __half& lo) {
    hi = __float2half_rn(v);
    lo = __float2half_rn(v - __half2float(hi));
}

// ---------------------------------------------------------------------------
// Merged transpose+split for all 3 weights x 2 layers: grid (32,32,6).
// ---------------------------------------------------------------------------
__global__ void transpose_split_all(const float* __restrict__ Wq,
                                    const float* __restrict__ Wk,
                                    const float* __restrict__ Wv,
                                    __half* __restrict__ dhi,
                                    __half* __restrict__ dlo) {
    __shared__ float t[32][33];
    int tx = threadIdx.x;
    int w = blockIdx.z >> 1, layer = blockIdx.z & 1;
    const float* src = ((w == 0) ? Wq : (w == 1) ? Wk : Wv) + (size_t)layer * D_ * D_;
    size_t doff = (size_t)(layer * 3 + w) * D_ * D_;
    int x = blockIdx.x * 32 + tx;
    int y0 = blockIdx.y * 32;
    #pragma unroll
    for (int j = threadIdx.y; j < 32; j += 8)
        t[j][tx] = src[(size_t)(y0 + j) * D_ + x];
    __syncthreads();
    #pragma unroll
    for (int j = threadIdx.y; j < 32; j += 8) {
        float v = t[tx][j];
        __half h, l; split_f16(v, h, l);
        size_t di = doff + (size_t)(blockIdx.x * 32 + j) * D_ + y0 + tx;
        dhi[di] = h; dlo[di] = l;
    }
}

// ---------------------------------------------------------------------------
// Merged QKV GEMM, fp16-split, ldmatrix, 512 threads (4x4 warp grid).
// Q,K: x3; V: x1. grid (24, 64), 2 CTA/SM (smem-capped) -> 32 warps/SM.
// ---------------------------------------------------------------------------
#define ROWB 80
#define PLANE (128*ROWB)       // 10240
#define STAGE_B (4*PLANE)      // 40960
#define GEMM_SMEM (2*STAGE_B)  // 81920

DI void gemm_issue(uint32_t sbase, int buf, const __half* Ah, const __half* Al,
                   const __half* Bh, const __half* Bl, int k0, int tid) {
    uint32_t st = sbase + buf * STAGE_B;
    const __half* srcs[4] = {Ah, Al, Bh, Bl};
    #pragma unroll
    for (int i = 0; i < 4; i++) {
        int c = tid + i * 512;
        int p = c >> 9;
        int cid = c & 511;
        int r = cid >> 2, cc = cid & 3;
        cp_async16(st + p * PLANE + r * ROWB + cc * 16,
                   srcs[p] + (size_t)r * D_ + k0 + cc * 8);
    }
}

__global__ void __launch_bounds__(512)
gemm_qkv(const __half* __restrict__ whh_l, const __half* __restrict__ whl_l,
         const float* __restrict__ bq, const float* __restrict__ bk,
         const float* __restrict__ bv) {
    extern __shared__ char smem[];
    uint32_t sbase = smem_u32(smem);
    int tid = threadIdx.x;
    int wid = tid >> 5, lane = tid & 31;
    int g = lane >> 2, tig = lane & 3;
    int warp_m = wid & 3, warp_n = wid >> 2;          // 4 x 4 warp grid
    int n_glob = blockIdx.x * 128;
    int which = n_glob >> 10;
    int n0 = n_glob & 1023;
    int m0 = blockIdx.y * 128;
    const __half* Ah = g_hh + (size_t)m0 * D_;
    const __half* Al = g_hl + (size_t)m0 * D_;
    const __half* Bh = whh_l + (size_t)which * D_ * D_ + (size_t)n0 * D_;
    const __half* Bl = whl_l + (size_t)which * D_ * D_ + (size_t)n0 * D_;
    const float* bias = (which == 0) ? bq : (which == 1) ? bk : bv;
    float* C = (which == 0) ? g_Q : (which == 1) ? g_K : g_V;
    bool x3 = (which != 2);

    float acc[2][4][4];
    #pragma unroll
    for (int i = 0; i < 2; i++)
        #pragma unroll
        for (int j = 0; j < 4; j++)
            #pragma unroll
            for (int q = 0; q < 4; q++) acc[i][j][q] = 0.f;

    gemm_issue(sbase, 0, Ah, Al, Bh, Bl, 0, tid);
    cp_commit();

    uint32_t a_lane = (uint32_t)(((lane & 7) + ((lane >> 3) & 1) * 8) * ROWB
                                 + ((lane >> 4) & 1) * 16);
    uint32_t b_lane = (uint32_t)((lane & 7) * ROWB + ((lane >> 4) & 1) * 8 * ROWB
                                 + ((lane >> 3) & 1) * 16);
    uint32_t arow0 = (uint32_t)(warp_m * 32) * ROWB;
    uint32_t brow0 = 2 * PLANE + (uint32_t)(warp_n * 32) * ROWB;

    for (int it = 0; it < 32; it++) {
        cp_wait<0>();
        __syncthreads();
        if (it + 1 < 32) {
            gemm_issue(sbase, (it + 1) & 1, Ah, Al, Bh, Bl, (it + 1) * 32, tid);
            cp_commit();
        }
        uint32_t st = sbase + (it & 1) * STAGE_B;
        #pragma unroll
        for (int ks = 0; ks < 2; ks++) {
            uint32_t ko = ks * 32;
            uint32_t ahi[2][4], alo[2][4];
            #pragma unroll
            for (int mt = 0; mt < 2; mt++) {
                uint32_t abase = st + arow0 + (uint32_t)(mt * 16) * ROWB + a_lane + ko;
                ldsm_x4(ahi[mt][0], ahi[mt][1], ahi[mt][2], ahi[mt][3], abase);
                ldsm_x4(alo[mt][0], alo[mt][1], alo[mt][2], alo[mt][3], abase + PLANE);
            }
            // Sweep 1: hi*hi for the warp's 4 nt
            #pragma unroll
            for (int p = 0; p < 2; p++) {
                uint32_t bb = st + brow0 + (uint32_t)(p * 16) * ROWB + b_lane + ko;
                uint32_t h0, h1, h2, h3;
                ldsm_x4(h0, h1, h2, h3, bb);
                mma_f16(acc[0][2*p],   ahi[0], h0, h1);
                mma_f16(acc[1][2*p],   ahi[1], h0, h1);
                mma_f16(acc[0][2*p+1], ahi[0], h2, h3);
                mma_f16(acc[1][2*p+1], ahi[1], h2, h3);
            }
            // Sweep 2: cross terms (x3 only); per-acc order hh -> hl -> lh
            if (x3) {
                #pragma unroll
                for (int p = 0; p < 2; p++) {
                    uint32_t bb = st + brow0 + (uint32_t)(p * 16) * ROWB + b_lane + ko;
                    uint32_t h0, h1, h2, h3, l0, l1, l2, l3;
                    ldsm_x4(h0, h1, h2, h3, bb);
                    ldsm_x4(l0, l1, l2, l3, bb + PLANE);
                    mma_f16(acc[0][2*p],   ahi[0], l0, l1);
                    mma_f16(acc[1][2*p],   ahi[1], l0, l1);
                    mma_f16(acc[0][2*p],   alo[0], h0, h1);
                    mma_f16(acc[1][2*p],   alo[1], h0, h1);
                    mma_f16(acc[0][2*p+1], ahi[0], l2, l3);
                    mma_f16(acc[1][2*p+1], ahi[1], l2, l3);
                    mma_f16(acc[0][2*p+1], alo[0], h2, h3);
                    mma_f16(acc[1][2*p+1], alo[1], h2, h3);
                }
            }
        }
    }

    #pragma unroll
    for (int mt = 0; mt < 2; mt++) {
        int row = m0 + warp_m * 32 + mt * 16 + g;
        #pragma unroll
        for (int nt = 0; nt < 4; nt++) {
            int col = n0 + warp_n * 32 + nt * 8 + tig * 2;
            float b0 = bias[col], b1 = bias[col + 1];
            float2 o0 = { acc[mt][nt][0] + b0, acc[mt][nt][1] + b1 };
            float2 o1 = { acc[mt][nt][2] + b0, acc[mt][nt][3] + b1 };
            *(float2*)(C + (size_t)row * D_ + col) = o0;
            *(float2*)(C + (size_t)(row + 8) * D_ + col) = o1;
        }
    }
}

// ---------------------------------------------------------------------------
// Scores rowmax tf32 x1 FILTER, single-barrier pipeline. (unchanged)
// ---------------------------------------------------------------------------
#define SC_SMEM (32768 + 2*32768 + 1024)   // 99328

DI void k_issue(uint32_t kbase, int buf, const float* Kg, int kt, int tid) {
    uint32_t st = kbase + buf * 32768;
    #pragma unroll
    for (int i = 0; i < 8; i++) {
        int c = tid + i * 256;
        int r = c >> 4, c16 = c & 15;
        int s = c16 >> 3, cc = c16 & 7;
        cp_async16(st + s * 16384 + r * 128 + ((cc ^ (r & 7)) << 4),
                   Kg + (size_t)(kt * 128 + r) * D_ + c16 * 4);
    }
}

__global__ void __launch_bounds__(256, 2)
scores_mma_kernel() {
    extern __shared__ char smem[];
    uint32_t sbase = smem_u32(smem);
    uint32_t kbase = sbase + 32768;
    float* redm = (float*)(smem + 32768 + 2 * 32768);
    int tid = threadIdx.x;
    int wid = tid >> 5, lane = tid & 31;
    int g = lane >> 2, tig = lane & 3;
    int warp_m = wid & 3, warp_n = wid >> 2;
    int qt = blockIdx.x, hh = blockIdx.y, b = blockIdx.z;

    const float* Qg = g_Q + ((size_t)(b * L_ + qt * 128)) * D_ + hh * DK_;
    const float* Kg = g_K + ((size_t)(b * L_)) * D_ + hh * DK_;

    k_issue(kbase, 0, Kg, 0, tid); cp_commit();

    #pragma unroll
    for (int i = 0; i < 8; i++) {
        int c = tid + i * 256;
        int r = c >> 4, c16 = c & 15;
        int s = c16 >> 3, cc = c16 & 7;
        float4 v = *(const float4*)(Qg + (size_t)r * D_ + c16 * 4);
        uint32_t dst = sbase + s * 16384 + r * 128 + ((cc ^ (r & 7)) << 4);
        asm volatile("st.shared.v4.f32 [%0], {%1,%2,%3,%4};" ::
            "r"(dst), "f"(v.x), "f"(v.y), "f"(v.z), "f"(v.w) : "memory");
    }

    float mx[2][2] = {{-3.0e38f, -3.0e38f}, {-3.0e38f, -3.0e38f}};

    for (int kt = 0; kt < 8; kt++) {
        cp_wait<0>();
        __syncthreads();
        if (kt + 1 < 8) {
            k_issue(kbase, (kt + 1) & 1, Kg, kt + 1, tid);
            cp_commit();
        }

        float acc[2][8][4];
        #pragma unroll
        for (int i = 0; i < 2; i++)
            #pragma unroll
            for (int j = 0; j < 8; j++)
                #pragma unroll
                for (int q = 0; q < 4; q++) acc[i][j][q] = 0.f;

        uint32_t stK = kbase + (kt & 1) * 32768;
        #pragma unroll
        for (int ks = 0; ks < 8; ks++) {
            int sub = (ks >> 2) * 16384, k2 = ks & 3;
            int c16a = ((2 * k2) ^ g) << 4;
            int c16b = ((2 * k2 + 1) ^ g) << 4;
            uint32_t ah[2][4];
            #pragma unroll
            for (int mt = 0; mt < 2; mt++) {
                uint32_t rowA = sbase + sub + (uint32_t)(warp_m * 32 + mt * 16 + g) * 128 + tig * 4;
                ah[mt][0] = lds_u32(rowA + c16a);
                ah[mt][1] = lds_u32(rowA + 1024 + c16a);
                ah[mt][2] = lds_u32(rowA + c16b);
                ah[mt][3] = lds_u32(rowA + 1024 + c16b);
            }
            #pragma unroll
            for (int nt = 0; nt < 8; nt++) {
                uint32_t rowB = stK + sub + (uint32_t)(warp_n * 64 + nt * 8 + g) * 128 + tig * 4;
                uint32_t bh0 = lds_u32(rowB + c16a);
                uint32_t bh1 = lds_u32(rowB + c16b);
                #pragma unroll
                for (int mt = 0; mt < 2; mt++)
                    mma_tf32(acc[mt][nt], ah[mt], bh0, bh1);
            }
        }
        #pragma unroll
        for (int mt = 0; mt < 2; mt++)
            #pragma unroll
            for (int nt = 0; nt < 8; nt++) {
                mx[mt][0] = fmaxf(mx[mt][0], fmaxf(acc[mt][nt][0], acc[mt][nt][1]));
                mx[mt][1] = fmaxf(mx[mt][1], fmaxf(acc[mt][nt][2], acc[mt][nt][3]));
            }
    }

    #pragma unroll
    for (int mt = 0; mt < 2; mt++)
        #pragma unroll
        for (int rp = 0; rp < 2; rp++) {
            float v = mx[mt][rp];
            v = fmaxf(v, __shfl_xor_sync(0xffffffff, v, 1));
            v = fmaxf(v, __shfl_xor_sync(0xffffffff, v, 2));
            if (tig == 0)
                redm[warp_n * 128 + warp_m * 32 + mt * 16 + rp * 8 + g] = v;
        }
    __syncthreads();
    if (tid < 128) {
        float m = fmaxf(redm[tid], redm[128 + tid]);
        g_rowmax[(b * H_ + hh) * L_ + qt * 128 + tid] = m;
    }
}

// ======================= reductions =========================

DI float bredSum(float v, float* red) {
    int tid = threadIdx.x;
    red[tid] = v; __syncthreads();
    #pragma unroll
    for (int off = 128; off > 0; off >>= 1) {
        if (tid < off) red[tid] += red[tid + off];
        __syncthreads();
    }
    float r = red[0]; __syncthreads(); return r;
}

DI float bredMax(float v, float* red) {
    int tid = threadIdx.x;
    red[tid] = v; __syncthreads();
    #pragma unroll
    for (int off = 128; off > 0; off >>= 1) {
        if (tid < off) red[tid] = fmaxf(red[tid], red[tid + off]);
        __syncthreads();
    }
    float r = red[0]; __syncthreads(); return r;
}

// ---------------------------------------------------------------------------
// Fused candidate pipeline: top-32 filter (shuffle argmax) -> exact fp32
// rescore -> exact top-6.
// ---------------------------------------------------------------------------
__global__ void __launch_bounds__(256)
cand_kernel() {
    __shared__ float s[1024];
    __shared__ float wv[8];
    __shared__ int   wi[8];
    __shared__ float rv[256];
    __shared__ float qs[CAND][64];
    __shared__ int   rows[CAND];
    __shared__ float Ks[64][68];
    __shared__ float rmx[CAND][64];
    int bh = blockIdx.x;
    int b = bh >> 4, hh = bh & 15;
    int tid = threadIdx.x;

    #pragma unroll
    for (int i = 0; i < 4; i++) s[tid + i*256] = g_rowmax[bh*L_ + tid + i*256];
    __syncthreads();
    for (int it = 0; it < CAND; it++) {
        float v = -3.0e38f; int idx = 1 << 30;
        #pragma unroll
        for (int i = 0; i < 4; i++) {
            int m = tid + i*256;
            if (s[m] > v) { v = s[m]; idx = m; }
        }
        #pragma unroll
        for (int off = 16; off > 0; off >>= 1) {
            float ov = __shfl_xor_sync(0xffffffff, v, off);
            int   oi = __shfl_xor_sync(0xffffffff, idx, off);
            if (ov > v || (ov == v && oi < idx)) { v = ov; idx = oi; }
        }
        if ((tid & 31) == 0) { wv[tid >> 5] = v; wi[tid >> 5] = idx; }
        __syncthreads();
        if (tid < 32) {
            float v2 = (tid < 8) ? wv[tid] : -3.0e38f;
            int   i2 = (tid < 8) ? wi[tid] : (1 << 30);
            #pragma unroll
            for (int off = 4; off > 0; off >>= 1) {
                float ov = __shfl_xor_sync(0xffffffff, v2, off);
                int   oi = __shfl_xor_sync(0xffffffff, i2, off);
                if (ov > v2 || (ov == v2 && oi < i2)) { v2 = ov; i2 = oi; }
            }
            if (tid == 0) { rows[it] = i2; s[i2] = -3.0e38f; }
        }
        __syncthreads();
    }

    {
        int c = tid >> 3, ch = tid & 7;
        const float4* qsrc = (const float4*)&g_Q[((size_t)(b * L_ + rows[c])) * D_ + hh * DK_];
        *(float4*)&qs[c][ch * 8]     = qsrc[ch * 2];
        *(float4*)&qs[c][ch * 8 + 4] = qsrc[ch * 2 + 1];
    }
    int ml = tid & 63;
    int cg = tid >> 6;
    float mx[8];
    #pragma unroll
    for (int i = 0; i < 8; i++) mx[i] = -3.0e38f;

    for (int tile = 0; tile < 16; tile++) {
        __syncthreads();
        #pragma unroll
        for (int i = 0; i < 4; i++) {
            int idx = tid + i * 256;
            int r = idx >> 4, cc = idx & 15;
            *(float4*)&Ks[r][cc * 4] =
                *(const float4*)&g_K[((size_t)(b * L_ + tile * 64 + r)) * D_ + hh * DK_ + cc * 4];
        }
        __syncthreads();
        float acc[8] = {0.f,0.f,0.f,0.f,0.f,0.f,0.f,0.f};
        #pragma unroll
        for (int k = 0; k < 16; k++) {
            float4 kv = *(float4*)&Ks[ml][k * 4];
            #pragma unroll
            for (int ci = 0; ci < 8; ci++) {
                float4 qv = *(float4*)&qs[cg * 8 + ci][k * 4];
                acc[ci] = fmaf(kv.x, qv.x, acc[ci]);
                acc[ci] = fmaf(kv.y, qv.y, acc[ci]);
                acc[ci] = fmaf(kv.z, qv.z, acc[ci]);
                acc[ci] = fmaf(kv.w, qv.w, acc[ci]);
            }
        }
        #pragma unroll
        for (int ci = 0; ci < 8; ci++) mx[ci] = fmaxf(mx[ci], acc[ci]);
    }
    __syncthreads();
    #pragma unroll
    for (int ci = 0; ci < 8; ci++) rmx[cg * 8 + ci][ml] = mx[ci];
    __syncthreads();
    if (tid < CAND) {
        float m = rmx[tid][0];
        #pragma unroll 8
        for (int j = 1; j < 64; j++) m = fmaxf(m, rmx[tid][j]);
        rv[tid] = m;
    }
    __syncthreads();

    if (tid == 0) {
        float v[CAND]; int id[CAND];
        #pragma unroll
        for (int i = 0; i < CAND; i++) { v[i] = rv[i]; id[i] = rows[i]; }
        for (int it = 0; it < U_; it++) {
            int best = 0; float bv = -3.0e38f; int bi = 1 << 30;
            #pragma unroll
            for (int i = 0; i < CAND; i++) {
                if (v[i] > bv || (v[i] == bv && id[i] < bi)) { bv = v[i]; bi = id[i]; best = i; }
            }
            g_top[bh*U_ + it] = bi;
            v[best] = -3.0e38f;
        }
    }
}

// ======================= elementwise / small kernels =======================

__global__ void embed_kernel(const float* __restrict__ x,
                             const float* __restrict__ emb_W,
                             const float* __restrict__ emb_b, int b0) {
    int l = blockIdx.x * 256 + threadIdx.x;
    int d = blockIdx.y;
    int b = blockIdx.z + b0;
    float acc = emb_b[d];
    #pragma unroll
    for (int p = 0; p < 16; p++)
        acc = fmaf(x[(b*16 + p)*L_ + l], emb_W[p*D_ + d], acc);
    const float C = -0.0089944730195f;
    float div = expf((float)(l & ~1) * C);
    float arg = (float)d * div;
    float pe = (l & 1) ? cosf(arg) : sinf(arg);
    size_t idx = (size_t)(b*L_ + d)*D_ + l;
    float val = acc + pe;
    g_h[idx] = val;
    __half h, lo; split_f16(val, h, lo);
    g_hh[idx] = h; g_hl[idx] = lo;
}

// ---------------------------------------------------------------------------
// Fused ctx for all 6 selected queries of one (b,h).
// ---------------------------------------------------------------------------
__global__ void __launch_bounds__(256)
ctx6_kernel() {
    __shared__ float q6[U_][64];
    __shared__ float sc[U_][1024];
    __shared__ float red[256];
    __shared__ float invs[U_];
    __shared__ int   rows6[U_];
    int hh = blockIdx.x, b = blockIdx.y;
    int tid = threadIdx.x;
    if (tid < U_) rows6[tid] = g_top[(b*H_ + hh)*U_ + tid];
    __syncthreads();
    if (tid < U_ * 16) {
        int u = tid >> 4, c = tid & 15;
        *(float4*)&q6[u][c*4] =
            *(const float4*)&g_Q[(size_t)(b*L_ + rows6[u])*D_ + hh*DK_ + c*4];
    }
    __syncthreads();

    for (int m = tid; m < 1024; m += 256) {
        const float* kr = &g_K[(size_t)(b*L_ + m)*D_ + hh*DK_];
        float a[U_] = {0.f, 0.f, 0.f, 0.f, 0.f, 0.f};
        #pragma unroll
        for (int k = 0; k < 64; k += 4) {
            float4 kv = *(const float4*)&kr[k];
            #pragma unroll
            for (int u = 0; u < U_; u++) {
                a[u] = fmaf(q6[u][k],   kv.x, a[u]);
                a[u] = fmaf(q6[u][k+1], kv.y, a[u]);
                a[u] = fmaf(q6[u][k+2], kv.z, a[u]);
                a[u] = fmaf(q6[u][k+3], kv.w, a[u]);
            }
        }
        #pragma unroll
        for (int u = 0; u < U_; u++) sc[u][m] = a[u] * 0.125f;
    }
    __syncthreads();

    for (int u = 0; u < U_; u++) {
        float v = -3.0e38f;
        for (int m = tid; m < 1024; m += 256) v = fmaxf(v, sc[u][m]);
        float smax = bredMax(v, red);
        float lsum = 0.f;
        for (int m = tid; m < 1024; m += 256) {
            float e = expf(sc[u][m] - smax);
            sc[u][m] = e; lsum += e;
        }
        float ssum = bredSum(lsum, red);
        if (tid == 0) invs[u] = 1.0f / ssum;
    }
    __syncthreads();

    int k = tid & 63, g = tid >> 6;
    const float* Vb = &g_V[(size_t)(b*L_)*D_ + hh*DK_ + k];
    float acc[U_] = {0.f, 0.f, 0.f, 0.f, 0.f, 0.f};
    for (int m = g*256; m < g*256 + 256; m++) {
        float vv = Vb[(size_t)m*D_];
        #pragma unroll
        for (int u = 0; u < U_; u++)
            acc[u] = fmaf(sc[u][m], vv, acc[u]);
    }
    __syncthreads();
    float* r2 = &sc[0][0];
    #pragma unroll
    for (int u = 0; u < U_; u++) r2[u*256 + tid] = acc[u];
    __syncthreads();
    if (tid < 64) {
        #pragma unroll
        for (int u = 0; u < U_; u++) {
            float c = (r2[u*256 + tid] + r2[u*256 + tid + 64] +
                       r2[u*256 + tid + 128] + r2[u*256 + tid + 192]) * invs[u];
            g_ctx[((b*H_ + hh)*U_ + u)*DK_ + tid] = c;
        }
    }
}

// ---------------------------------------------------------------------------
// Fused LN1 + FFN + LN2 for 8 consecutive rows.
// ---------------------------------------------------------------------------
#define RPB 8
__global__ void __launch_bounds__(256)
ln1_ffn_kernel(const float* __restrict__ Wo, const float* __restrict__ bo,
               const float* __restrict__ g1, const float* __restrict__ b1g,
               const float* __restrict__ W1, const float* __restrict__ b1f,
               const float* __restrict__ W2, const float* __restrict__ b2f,
               const float* __restrict__ g2, const float* __restrict__ b2g) {
    __shared__ float hs[RPB][1024];
    __shared__ float pr[256][RPB];
    __shared__ float tsh[RPB][32];
    __shared__ float red[256];
    __shared__ int   tops[96];
    __shared__ float csh[64];
    int row0 = blockIdx.x * RPB;
    int b = row0 >> 10;
    int tid = threadIdx.x;
    if (tid < 96) tops[tid] = g_top[b*96 + tid];

    float4 hv[RPB];
    float4 bo4 = *(const float4*)&bo[tid*4];
    #pragma unroll
    for (int r = 0; r < RPB; r++) {
        hv[r] = *(const float4*)&g_h[(size_t)(row0 + r)*D_ + tid*4];
        hv[r].x += bo4.x; hv[r].y += bo4.y; hv[r].z += bo4.z; hv[r].w += bo4.w;
    }
    __syncthreads();

    for (int hh = 0; hh < H_; hh++) {
        for (int u = 0; u < U_; u++) {
            int srow = tops[hh*U_ + u];
            int rr = b*1024 + srow - row0;
            if (rr >= 0 && rr < RPB) {
                if (tid < 16)
                    *(float4*)&csh[tid*4] =
                        *(const float4*)&g_ctx[((b*H_ + hh)*U_ + u)*DK_ + tid*4];
                __syncthreads();
                #pragma unroll 8
                for (int k = 0; k < 64; k++) {
                    float c = csh[k];
                    float4 w = *(const float4*)&Wo[(size_t)(hh*64 + k)*D_ + tid*4];
                    hv[rr].x = fmaf(c, w.x, hv[rr].x);
                    hv[rr].y = fmaf(c, w.y, hv[rr].y);
                    hv[rr].z = fmaf(c, w.z, hv[rr].z);
                    hv[rr].w = fmaf(c, w.w, hv[rr].w);
                }
                __syncthreads();
            }
        }
    }

    {
        float4 gv = *(const float4*)&g1[tid*4];
        float4 bv = *(const float4*)&b1g[tid*4];
        #pragma unroll
        for (int r = 0; r < RPB; r++) {
            float mean = bredSum(hv[r].x + hv[r].y + hv[r].z + hv[r].w, red) * (1.0f/1024.0f);
            float cx = hv[r].x - mean, cy = hv[r].y - mean,
                  cz = hv[r].z - mean, cw = hv[r].w - mean;
            float var = bredSum(cx*cx + cy*cy + cz*cz + cw*cw, red) * (1.0f/1024.0f);
            float rstd = rsqrtf(var + 1e-5f);
            float4 o = { cx*rstd*gv.x + bv.x, cy*rstd*gv.y + bv.y,
                         cz*rstd*gv.z + bv.z, cw*rstd*gv.w + bv.w };
            *(float4*)&hs[r][tid*4] = o;
        }
    }
    __syncthreads();

    int j = tid & 31, grp = tid >> 5;
    float acc[RPB];
    #pragma unroll
    for (int r = 0; r < RPB; r++) acc[r] = 0.f;
    for (int f = grp*128; f < grp*128 + 128; f++) {
        float w = W1[f*FF_ + j];
        #pragma unroll
        for (int r = 0; r < RPB; r++) acc[r] = fmaf(hs[r][f], w, acc[r]);
    }
    #pragma unroll
    for (int r = 0; r < RPB; r++) pr[tid][r] = acc[r];
    __syncthreads();
    if (tid < 32) {
        #pragma unroll
        for (int r = 0; r < RPB; r++) {
            float t = 0.f;
            #pragma unroll
            for (int gq = 0; gq < 8; gq++) t += pr[gq*32 + tid][r];
            t += b1f[tid];
            tsh[r][tid] = fmaxf(t, 0.f);
        }
    }
    __syncthreads();

    float4 y[RPB];
    #pragma unroll
    for (int r = 0; r < RPB; r++) y[r] = *(float4*)&hs[r][tid*4];
    for (int jj = 0; jj < 32; jj++) {
        float4 w2 = *(const float4*)&W2[jj*D_ + tid*4];
        #pragma unroll
        for (int r = 0; r < RPB; r++) {
            float t = tsh[r][jj];
            y[r].x = fmaf(t, w2.x, y[r].x); y[r].y = fmaf(t, w2.y, y[r].y);
            y[r].z = fmaf(t, w2.z, y[r].z); y[r].w = fmaf(t, w2.w, y[r].w);
        }
    }
    float4 b2v = *(const float4*)&b2f[tid*4];
    float4 gv2 = *(const float4*)&g2[tid*4];
    float4 bv2 = *(const float4*)&b2g[tid*4];
    #pragma unroll
    for (int r = 0; r < RPB; r++) {
        y[r].x += b2v.x; y[r].y += b2v.y; y[r].z += b2v.z; y[r].w += b2v.w;
        float mean = bredSum(y[r].x + y[r].y + y[r].z + y[r].w, red) * (1.0f/1024.0f);
        float cx = y[r].x - mean, cy = y[r].y - mean, cz = y[r].z - mean, cw = y[r].w - mean;
        float var = bredSum(cx*cx + cy*cy + cz*cz + cw*cw, red) * (1.0f/1024.0f);
        float rstd = rsqrtf(var + 1e-5f);
        float4 o = { cx*rstd*gv2.x + bv2.x, cy*rstd*gv2.y + bv2.y,
                     cz*rstd*gv2.z + bv2.z, cw*rstd*gv2.w + bv2.w };
        size_t idx = (size_t)(row0 + r)*D_ + tid*4;
        *(float4*)&g_h[idx] = o;
        __half h0, l0, h1, l1, h2, l2, h3, l3;
        split_f16(o.x, h0, l0); split_f16(o.y, h1, l1);
        split_f16(o.z, h2, l2); split_f16(o.w, h3, l3);
        *(__half2*)&g_hh[idx]     = __halves2half2(h0, h1);
        *(__half2*)&g_hh[idx + 2] = __halves2half2(h2, h3);
        *(__half2*)&g_hl[idx]     = __halves2half2(l0, l1);
        *(__half2*)&g_hl[idx + 2] = __halves2half2(l2, l3);
    }
}

// ---------------------------------------------------------------------------
// Mean over sequence (two-phase), then parallel out projection.
// ---------------------------------------------------------------------------
__global__ void mean_part_kernel() {
    int f = blockIdx.x * 256 + threadIdx.x;
    int b = blockIdx.y, z = blockIdx.z;
    float acc = 0.f;
    for (int s = z*128; s < z*128 + 128; s++)
        acc += g_h[(size_t)(b*L_ + s)*D_ + f];
    g_meanp[(z*B_ + b)*D_ + f] = acc;
}

__global__ void mean_red_kernel() {
    int f = blockIdx.x * 256 + threadIdx.x;
    int b = blockIdx.y;
    float acc = 0.f;
    #pragma unroll
    for (int z = 0; z < 8; z++) acc += g_meanp[(z*B_ + b)*D_ + f];
    g_mean[b*D_ + f] = acc * (1.0f/1024.0f);
}

__global__ void __launch_bounds__(256)
outproj_kernel(const float* __restrict__ outW,
               const float* __restrict__ outb,
               float* __restrict__ out) {
    __shared__ float red[256];
    int b = blockIdx.x, j = blockIdx.y;
    int tid = threadIdx.x;
    float acc = 0.f;
    for (int f = tid; f < D_; f += 256)
        acc = fmaf(g_mean[b*D_ + f], outW[(size_t)f*HZN_ + j], acc);
    red[tid] = acc; __syncthreads();
    #pragma unroll
    for (int off = 128; off > 0; off >>= 1) {
        if (tid < off) red[tid] += red[tid + off];
        __syncthreads();
    }
    if (tid == 0) out[b*HZN_ + j] = red[0] + outb[j];
}

// ---------------------------------------------------------------------------
extern "C" void kernel_launch(void* const* d_in, const int* in_sizes, int n_in,
                              void* d_out, int out_size) {
    const float* x     = (const float*)d_in[0];
    const float* emb_W = (const float*)d_in[1];
    const float* emb_b = (const float*)d_in[2];
    const float* Wq    = (const float*)d_in[3];
    const float* bq    = (const float*)d_in[4];
    const float* Wk    = (const float*)d_in[5];
    const float* bk    = (const float*)d_in[6];
    const float* Wv    = (const float*)d_in[7];
    const float* bv    = (const float*)d_in[8];
    const float* Wo    = (const float*)d_in[9];
    const float* bo    = (const float*)d_in[10];
    const float* W1    = (const float*)d_in[11];
    const float* b1    = (const float*)d_in[12];
    const float* W2    = (const float*)d_in[13];
    const float* b2    = (const float*)d_in[14];
    const float* ln1g  = (const float*)d_in[15];
    const float* ln1b  = (const float*)d_in[16];
    const float* ln2g  = (const float*)d_in[17];
    const float* ln2b  = (const float*)d_in[18];
    const float* outW  = (const float*)d_in[19];
    const float* outb  = (const float*)d_in[20];
    float* out = (float*)d_out;

    __half *whh, *whl;
    cudaGetSymbolAddress((void**)&whh, g_whh);
    cudaGetSymbolAddress((void**)&whl, g_whl);

    cudaFuncSetAttribute(gemm_qkv, cudaFuncAttributeMaxDynamicSharedMemorySize, GEMM_SMEM);
    cudaFuncSetAttribute(scores_mma_kernel, cudaFuncAttributeMaxDynamicSharedMemorySize, SC_SMEM);

    transpose_split_all<<<dim3(32, 32, 6), dim3(32, 8)>>>(Wq, Wk, Wv, whh, whl);
    embed_kernel<<<dim3(4, 1024, 4), 256>>>(x, emb_W, emb_b, 0);
    embed_kernel<<<dim3(4, 1024, 4), 256>>>(x, emb_W, emb_b, 4);

    for (int layer = 0; layer < 2; layer++) {
        size_t boff = (size_t)layer * D_;
        size_t woff = (size_t)layer * D_ * D_;
        size_t soff = (size_t)layer * 3 * D_ * D_;
        gemm_qkv<<<dim3(24, 64), 512, GEMM_SMEM>>>(whh + soff, whl + soff,
                                                   bq + boff, bk + boff, bv + boff);
        scores_mma_kernel<<<dim3(8, 16, 8), 256, SC_SMEM>>>();
        cand_kernel<<<128, 256>>>();
        ctx6_kernel<<<dim3(H_, B_), 256>>>();
        ln1_ffn_kernel<<<NROWS/RPB, 256>>>(Wo + woff, bo + boff,
                                           ln1g + boff, ln1b + boff,
                                           W1 + (size_t)layer*D_*FF_, b1 + (size_t)layer*FF_,
                                           W2 + (size_t)layer*FF_*D_, b2 + boff,
                                           ln2g + boff, ln2b + boff);
    }
    mean_part_kernel<<<dim3(4, 8, 8), 256>>>();
    mean_red_kernel<<<dim3(4, 8), 256>>>();
    outproj_kernel<<<dim3(8, HZN_), 256>>>(outW, outb, out);
}